// round 1
// baseline (speedup 1.0000x reference)
#include <cuda_runtime.h>
#include <math.h>

#define T_STEPS 512
#define NTOK    32643
#define HID     512
#define BM 128
#define BJ 32
#define BN 96          // 3 gate strips (i, g, o) of BJ columns each
#define BK 32
#define LDSM 36        // BK + 4 pad -> conflict-free fragment reads, 16B-aligned vector stores
#define NTHREADS 128
#define SMEM_WORDS (2*BM*LDSM + 2*BN*LDSM)   // 16128 words = 63 KB
#define SMEM_BYTES (SMEM_WORDS * 4)

// Scratch for the (deterministic) gather index, rebuilt every launch.
__device__ int g_idx[NTOK];

__device__ __forceinline__ int bsz(int i) {
    int v = (128 * (T_STEPS - i)) >> 9;   // (128*(512-i)) // 512
    return v < 1 ? 1 : v;
}

// Build idx = concat_i ( i*bs[i] + arange(bs[i]) ).  512 blocks, one per timestep.
__global__ void k_build_idx() {
    __shared__ int off;
    int t = blockIdx.x;
    if (threadIdx.x == 0) {
        int s = 0;
        for (int i = 0; i < t; i++) s += bsz(i);
        off = s;
    }
    __syncthreads();
    int b = bsz(t);
    if ((int)threadIdx.x < b) g_idx[off + threadIdx.x] = t * b + (int)threadIdx.x;
}

__device__ __forceinline__ unsigned f2tf(float x) {
    unsigned u;
    asm("cvt.rna.tf32.f32 %0, %1;" : "=r"(u) : "f"(x));
    return u;
}

__device__ __forceinline__ void mma8(float* d, const unsigned* a, const unsigned* b) {
    asm volatile(
        "mma.sync.aligned.m16n8k8.row.col.f32.tf32.tf32.f32 "
        "{%0,%1,%2,%3}, {%4,%5,%6,%7}, {%8,%9}, {%0,%1,%2,%3};\n"
        : "+f"(d[0]), "+f"(d[1]), "+f"(d[2]), "+f"(d[3])
        : "r"(a[0]), "r"(a[1]), "r"(a[2]), "r"(a[3]), "r"(b[0]), "r"(b[1]));
}

// One LSTM cell (zero state): out = activations( A @ Wsel^T + bias ), gates i,g,o only.
// Wsel rows: i -> W[0..512), g -> W[1024..1536), o -> W[1536..2048).
__global__ __launch_bounds__(NTHREADS)
void lstm_cell_gemm(const float* __restrict__ A, int use_idx,
                    const float* __restrict__ W,
                    const float* __restrict__ bih, const float* __restrict__ bhh,
                    float* __restrict__ out_h, float* __restrict__ out_c,
                    float* __restrict__ out_h2)
{
    extern __shared__ __align__(16) unsigned sm[];
    unsigned* As = sm;                    // [2*BM][LDSM] tf32 bits, row-major [m][k]
    unsigned* Bs = sm + 2 * BM * LDSM;    // [2*BN][LDSM] tf32 bits, [n][k]

    const int bj = blockIdx.x;            // 0..15  (j tile)
    const int bm = blockIdx.y;            // 0..255 (m tile)
    const int m0 = bm * BM, j0 = bj * BJ;
    const int tid = threadIdx.x, lane = tid & 31, wid = tid >> 5;
    const int wm = (wid >> 1) * 64;       // warp m offset
    const int wn = (wid & 1) * 48;        // warp n offset
    const int kq = (tid & 7) * 4;         // float offset within a K row (float4 lane)

    // Per-thread gmem row offsets (constant across K loop)
    int arow[8]; bool avalid[8];
#pragma unroll
    for (int i = 0; i < 8; i++) {
        int m = (tid >> 3) + i * 16;
        int gm = m0 + m;
        avalid[i] = (gm < NTOK);
        int src = 0;
        if (avalid[i]) src = use_idx ? g_idx[gm] : gm;
        arow[i] = src * HID + kq;
    }
    int brow[6];
#pragma unroll
    for (int i = 0; i < 6; i++) {
        int n = (tid >> 3) + i * 16;
        int u = n & 31;
        int wr = (n < 32 ? 0 : (n < 64 ? 1024 : 1536)) + j0 + u;
        brow[i] = wr * HID + kq;
    }

    float4 areg[8], breg[6];
    float acc[4][6][4];
#pragma unroll
    for (int mi = 0; mi < 4; mi++)
#pragma unroll
        for (int ni = 0; ni < 6; ni++)
#pragma unroll
            for (int r = 0; r < 4; r++) acc[mi][ni][r] = 0.f;

    // ---- prologue: load + store stage 0 into buf 0 ----
#pragma unroll
    for (int i = 0; i < 8; i++)
        areg[i] = avalid[i] ? *(const float4*)(A + arow[i]) : make_float4(0.f, 0.f, 0.f, 0.f);
#pragma unroll
    for (int i = 0; i < 6; i++)
        breg[i] = *(const float4*)(W + brow[i]);
#pragma unroll
    for (int i = 0; i < 8; i++) {
        uint4 v = make_uint4(f2tf(areg[i].x), f2tf(areg[i].y), f2tf(areg[i].z), f2tf(areg[i].w));
        *(uint4*)&As[((tid >> 3) + i * 16) * LDSM + kq] = v;
    }
#pragma unroll
    for (int i = 0; i < 6; i++) {
        uint4 v = make_uint4(f2tf(breg[i].x), f2tf(breg[i].y), f2tf(breg[i].z), f2tf(breg[i].w));
        *(uint4*)&Bs[((tid >> 3) + i * 16) * LDSM + kq] = v;
    }

    const int r = lane >> 2, c = lane & 3;

#pragma unroll 1
    for (int kt = 0; kt < HID / BK; kt++) {
        __syncthreads();
        const int kofs = (kt + 1) * BK;
        const bool more = kofs < HID;
        if (more) {
#pragma unroll
            for (int i = 0; i < 8; i++)
                areg[i] = avalid[i] ? *(const float4*)(A + arow[i] + kofs)
                                    : make_float4(0.f, 0.f, 0.f, 0.f);
#pragma unroll
            for (int i = 0; i < 6; i++)
                breg[i] = *(const float4*)(W + brow[i] + kofs);
        }

        const unsigned* Ab = As + (kt & 1) * BM * LDSM;
        const unsigned* Bb = Bs + (kt & 1) * BN * LDSM;
#pragma unroll
        for (int ks = 0; ks < BK / 8; ks++) {
            const int kb = ks * 8;
            unsigned af[4][4], bf[6][2];
#pragma unroll
            for (int mi = 0; mi < 4; mi++) {
                int mr = wm + mi * 16 + r;
                af[mi][0] = Ab[mr * LDSM + kb + c];
                af[mi][1] = Ab[(mr + 8) * LDSM + kb + c];
                af[mi][2] = Ab[mr * LDSM + kb + c + 4];
                af[mi][3] = Ab[(mr + 8) * LDSM + kb + c + 4];
            }
#pragma unroll
            for (int ni = 0; ni < 6; ni++) {
                int nr = wn + ni * 8 + r;
                bf[ni][0] = Bb[nr * LDSM + kb + c];
                bf[ni][1] = Bb[nr * LDSM + kb + c + 4];
            }
#pragma unroll
            for (int mi = 0; mi < 4; mi++)
#pragma unroll
                for (int ni = 0; ni < 6; ni++)
                    mma8(acc[mi][ni], af[mi], bf[ni]);
        }

        if (more) {
            unsigned* Aw = As + ((kt + 1) & 1) * BM * LDSM;
            unsigned* Bw = Bs + ((kt + 1) & 1) * BN * LDSM;
#pragma unroll
            for (int i = 0; i < 8; i++) {
                uint4 v = make_uint4(f2tf(areg[i].x), f2tf(areg[i].y), f2tf(areg[i].z), f2tf(areg[i].w));
                *(uint4*)&Aw[((tid >> 3) + i * 16) * LDSM + kq] = v;
            }
#pragma unroll
            for (int i = 0; i < 6; i++) {
                uint4 v = make_uint4(f2tf(breg[i].x), f2tf(breg[i].y), f2tf(breg[i].z), f2tf(breg[i].w));
                *(uint4*)&Bw[((tid >> 3) + i * 16) * LDSM + kq] = v;
            }
        }
    }
    __syncthreads();

    // ---- epilogue: stage gates in smem, then fused LSTM pointwise ----
    float* Gs = (float*)sm;               // [BM][98]  (12544 words <= 16128)
#pragma unroll
    for (int mi = 0; mi < 4; mi++) {
#pragma unroll
        for (int ni = 0; ni < 6; ni++) {
            int row = wm + mi * 16 + r;
            int col = wn + ni * 8 + 2 * c;
            *(float2*)&Gs[row * 98 + col]       = make_float2(acc[mi][ni][0], acc[mi][ni][1]);
            *(float2*)&Gs[(row + 8) * 98 + col] = make_float2(acc[mi][ni][2], acc[mi][ni][3]);
        }
    }
    __syncthreads();

    for (int e = tid; e < BM * BJ; e += NTHREADS) {
        int m = e >> 5, j = e & 31;
        int gm = m0 + m;
        if (gm >= NTOK) continue;
        int jg = j0 + j;
        float iv = Gs[m * 98 + j]      + bih[jg]         + bhh[jg];
        float gv = Gs[m * 98 + 32 + j] + bih[1024 + jg]  + bhh[1024 + jg];
        float ov = Gs[m * 98 + 64 + j] + bih[1536 + jg]  + bhh[1536 + jg];
        float cc = (1.f / (1.f + expf(-iv))) * tanhf(gv);
        float hh = (1.f / (1.f + expf(-ov))) * tanhf(cc);
        size_t off = (size_t)gm * HID + jg;
        out_h[off] = hh;
        out_c[off] = cc;
        if (out_h2) out_h2[off] = hh;
    }
}

extern "C" void kernel_launch(void* const* d_in, const int* in_sizes, int n_in,
                              void* d_out, int out_size)
{
    (void)in_sizes; (void)n_in; (void)out_size;
    const float* packed_x = (const float*)d_in[0];
    const float* W1   = (const float*)d_in[2];
    const float* bih1 = (const float*)d_in[4];
    const float* bhh1 = (const float*)d_in[5];
    const float* W2   = (const float*)d_in[6];
    const float* bih2 = (const float*)d_in[8];
    const float* bhh2 = (const float*)d_in[9];
    const float* W3   = (const float*)d_in[10];
    const float* bih3 = (const float*)d_in[12];
    const float* bhh3 = (const float*)d_in[13];
    const float* W4   = (const float*)d_in[14];
    const float* bih4 = (const float*)d_in[16];
    const float* bhh4 = (const float*)d_in[17];

    float* out = (float*)d_out;
    const size_t NH = (size_t)NTOK * HID;
    float* o_dup = out;            // output == h4
    float* h1 = out + 1 * NH; float* c1 = out + 2 * NH;
    float* h2 = out + 3 * NH; float* c2 = out + 4 * NH;
    float* h3 = out + 5 * NH; float* c3 = out + 6 * NH;
    float* h4 = out + 7 * NH; float* c4 = out + 8 * NH;

    cudaFuncSetAttribute(lstm_cell_gemm,
                         cudaFuncAttributeMaxDynamicSharedMemorySize, SMEM_BYTES);

    k_build_idx<<<T_STEPS, 128>>>();

    dim3 grid(HID / BJ, (NTOK + BM - 1) / BM);   // (16, 256)
    lstm_cell_gemm<<<grid, NTHREADS, SMEM_BYTES>>>(packed_x, 1, W1, bih1, bhh1, h1, c1, nullptr);
    lstm_cell_gemm<<<grid, NTHREADS, SMEM_BYTES>>>(h1,       0, W2, bih2, bhh2, h2, c2, nullptr);
    lstm_cell_gemm<<<grid, NTHREADS, SMEM_BYTES>>>(h2,       0, W3, bih3, bhh3, h3, c3, nullptr);
    lstm_cell_gemm<<<grid, NTHREADS, SMEM_BYTES>>>(h3,       0, W4, bih4, bhh4, h4, c4, o_dup);
}

// round 2
// speedup vs baseline: 1.2557x; 1.2557x over previous
#include <cuda_runtime.h>
#include <math.h>

#define T_STEPS 512
#define NTOK    32643
#define NPAD    32768
#define HID     512
#define BM 128
#define BJ 32
#define BN 96          // 3 gate strips (i, g, o) of BJ columns each
#define BK 32
#define LDSM 36        // BK + 4 pad; 144B row pitch (16B aligned), conflict-free frag reads
#define NTHREADS 256
#define KTILES (HID / BK)          // 16
#define A_WORDS (BM * LDSM)        // 4608
#define B_WORDS (BN * LDSM)        // 3456
#define SMEM_WORDS (2 * A_WORDS + 2 * B_WORDS)  // 16128 words = 63 KB
#define SMEM_BYTES (SMEM_WORDS * 4)

// ---- persistent scratch (zero-initialized at module load) ----
__device__ int   g_idx[NTOK];
__device__ float g_A0[(size_t)NPAD * HID];   // ping: tf32-rounded activations
__device__ float g_A1[(size_t)NPAD * HID];   // pong
__device__ float g_W[(size_t)4 * 1536 * HID]; // tf32-rounded W rows (i,g,o only) per layer

__device__ __forceinline__ int bsz(int i) {
    int v = (128 * (T_STEPS - i)) >> 9;
    return v < 1 ? 1 : v;
}

__global__ void k_build_idx() {
    __shared__ int off;
    int t = blockIdx.x;
    if (threadIdx.x == 0) {
        int s = 0;
        for (int i = 0; i < t; i++) s += bsz(i);
        off = s;
    }
    __syncthreads();
    int b = bsz(t);
    if ((int)threadIdx.x < b) g_idx[off + threadIdx.x] = t * b + (int)threadIdx.x;
}

__device__ __forceinline__ float rtf(float x) {
    unsigned u;
    asm("cvt.rna.tf32.f32 %0, %1;" : "=r"(u) : "f"(x));
    return __uint_as_float(u);
}

// Gather packed_x rows via g_idx, round to tf32, write g_A0 (pad rows zero).
__global__ void k_gather(const float* __restrict__ x) {
    int row = blockIdx.x;
    float4* dst = (float4*)(g_A0 + (size_t)row * HID);
    if (row < NTOK) {
        const float4* src = (const float4*)(x + (size_t)g_idx[row] * HID);
        for (int i = threadIdx.x; i < HID / 4; i += blockDim.x) {
            float4 v = src[i];
            v.x = rtf(v.x); v.y = rtf(v.y); v.z = rtf(v.z); v.w = rtf(v.w);
            dst[i] = v;
        }
    } else {
        for (int i = threadIdx.x; i < HID / 4; i += blockDim.x)
            dst[i] = make_float4(0.f, 0.f, 0.f, 0.f);
    }
}

// Copy i,g,o rows of each layer's W (skip f), rounded to tf32, into g_W.
__global__ void k_round_w(const float* __restrict__ W1, const float* __restrict__ W2,
                          const float* __restrict__ W3, const float* __restrict__ W4) {
    int l = blockIdx.y;
    const float* W = (l == 0) ? W1 : (l == 1) ? W2 : (l == 2) ? W3 : W4;
    int t = blockIdx.x * blockDim.x + threadIdx.x;  // float4 id, 196608 total
    int n = t >> 7;                  // 0..1535
    int col = (t & 127) * 4;
    int srow = n + (n >= 512 ? 512 : 0);   // i:0..511, g:1024.., o:1536..
    float4 v = *(const float4*)(W + (size_t)srow * HID + col);
    v.x = rtf(v.x); v.y = rtf(v.y); v.z = rtf(v.z); v.w = rtf(v.w);
    *(float4*)(g_W + ((size_t)l * 1536 + n) * HID + col) = v;
}

__device__ __forceinline__ void cpa16(unsigned d, const void* s) {
    asm volatile("cp.async.cg.shared.global [%0], [%1], 16;\n" :: "r"(d), "l"(s));
}

__device__ __forceinline__ void mma8(float* d, const unsigned* a, const unsigned* b) {
    asm volatile(
        "mma.sync.aligned.m16n8k8.row.col.f32.tf32.tf32.f32 "
        "{%0,%1,%2,%3}, {%4,%5,%6,%7}, {%8,%9}, {%0,%1,%2,%3};\n"
        : "+f"(d[0]), "+f"(d[1]), "+f"(d[2]), "+f"(d[3])
        : "r"(a[0]), "r"(a[1]), "r"(a[2]), "r"(a[3]), "r"(b[0]), "r"(b[1]));
}

__global__ __launch_bounds__(NTHREADS, 2)
void lstm_cell_gemm(int layer,
                    const float* __restrict__ bih, const float* __restrict__ bhh,
                    float* __restrict__ out_h, float* __restrict__ out_c,
                    float* __restrict__ out_h2)
{
    const float* A    = (layer & 1) ? g_A1 : g_A0;
    float*       Anext = (layer == 3) ? nullptr : ((layer & 1) ? g_A0 : g_A1);
    const float* Wl   = g_W + (size_t)layer * 1536 * HID;

    extern __shared__ __align__(16) float sm[];
    const int bj = blockIdx.x, bm = blockIdx.y;
    const int m0 = bm * BM, j0 = bj * BJ;
    const int tid = threadIdx.x, lane = tid & 31, wid = tid >> 5;
    const int wm = (wid >> 1) * 32;       // 4 warps along m (32 rows each)
    const int wn = (wid & 1) * 48;        // 2 warps along n (48 cols each)
    const int r = lane >> 2, c = lane & 3;

    // cp.async chunk mapping (16B per thread per chunk)
    const float* asrc[4]; unsigned adst[4];
#pragma unroll
    for (int i = 0; i < 4; i++) {
        int cid = tid + i * NTHREADS;          // 0..1023
        int m = cid >> 3, kc = (cid & 7) * 4;
        asrc[i] = A + (size_t)(m0 + m) * HID + kc;
        adst[i] = (unsigned)(m * LDSM + kc);
    }
    const float* bsrc[3]; unsigned bdst[3];
#pragma unroll
    for (int i = 0; i < 3; i++) {
        int cid = tid + i * NTHREADS;          // 0..767
        int n = cid >> 3, kc = (cid & 7) * 4;
        int wr = (n >> 5) * 512 + j0 + (n & 31);  // strip*512 + j0 + u in g_W layer
        bsrc[i] = Wl + (size_t)wr * HID + kc;
        bdst[i] = (unsigned)(2 * A_WORDS + n * LDSM + kc);
    }
    unsigned smbase = (unsigned)__cvta_generic_to_shared(sm);

    auto issue = [&](int kt) {
        int s = kt & 1;
        unsigned ab = smbase + (unsigned)(s * A_WORDS) * 4u;
        unsigned bb = smbase + (unsigned)(s * B_WORDS) * 4u;
        const int ko = kt * BK;
#pragma unroll
        for (int i = 0; i < 4; i++) cpa16(ab + adst[i] * 4u, asrc[i] + ko);
#pragma unroll
        for (int i = 0; i < 3; i++) cpa16(bb + bdst[i] * 4u, bsrc[i] + ko);
        asm volatile("cp.async.commit_group;\n");
    };

    float acc[2][6][4];
#pragma unroll
    for (int mi = 0; mi < 2; mi++)
#pragma unroll
        for (int ni = 0; ni < 6; ni++)
#pragma unroll
            for (int q = 0; q < 4; q++) acc[mi][ni][q] = 0.f;

    issue(0);

#pragma unroll 1
    for (int kt = 0; kt < KTILES; kt++) {
        asm volatile("cp.async.wait_group 0;\n");
        __syncthreads();
        if (kt + 1 < KTILES) issue(kt + 1);

        const unsigned* Ab = (const unsigned*)sm + (kt & 1) * A_WORDS;
        const unsigned* Bb = (const unsigned*)sm + 2 * A_WORDS + (kt & 1) * B_WORDS;
#pragma unroll
        for (int ks = 0; ks < BK / 8; ks++) {
            const int kb = ks * 8;
            unsigned af[2][4], bf[6][2];
#pragma unroll
            for (int mi = 0; mi < 2; mi++) {
                int mr = wm + mi * 16 + r;
                af[mi][0] = Ab[mr * LDSM + kb + c];
                af[mi][1] = Ab[(mr + 8) * LDSM + kb + c];
                af[mi][2] = Ab[mr * LDSM + kb + c + 4];
                af[mi][3] = Ab[(mr + 8) * LDSM + kb + c + 4];
            }
#pragma unroll
            for (int ni = 0; ni < 6; ni++) {
                int nr = wn + ni * 8 + r;
                bf[ni][0] = Bb[nr * LDSM + kb + c];
                bf[ni][1] = Bb[nr * LDSM + kb + c + 4];
            }
#pragma unroll
            for (int mi = 0; mi < 2; mi++)
#pragma unroll
                for (int ni = 0; ni < 6; ni++)
                    mma8(acc[mi][ni], af[mi], bf[ni]);
        }
    }
    __syncthreads();   // all compute done before smem reuse

    // ---- epilogue: stage gates (i,g,o strips) in smem, then fused pointwise ----
    float* Gs = sm;    // [BM][98] = 12544 words <= 16128
#pragma unroll
    for (int mi = 0; mi < 2; mi++) {
#pragma unroll
        for (int ni = 0; ni < 6; ni++) {
            int row = wm + mi * 16 + r;
            int col = wn + ni * 8 + 2 * c;
            *(float2*)&Gs[row * 98 + col]       = make_float2(acc[mi][ni][0], acc[mi][ni][1]);
            *(float2*)&Gs[(row + 8) * 98 + col] = make_float2(acc[mi][ni][2], acc[mi][ni][3]);
        }
    }
    __syncthreads();

    for (int e = tid; e < BM * BJ; e += NTHREADS) {
        int m = e >> 5, j = e & 31;
        int gm = m0 + m;
        if (gm >= NTOK) continue;
        int jg = j0 + j;
        float iv = Gs[m * 98 + j]      + bih[jg]        + bhh[jg];
        float gv = Gs[m * 98 + 32 + j] + bih[1024 + jg] + bhh[1024 + jg];
        float ov = Gs[m * 98 + 64 + j] + bih[1536 + jg] + bhh[1536 + jg];
        float cc = (1.f / (1.f + expf(-iv))) * tanhf(gv);
        float hh = (1.f / (1.f + expf(-ov))) * tanhf(cc);
        size_t off = (size_t)gm * HID + jg;
        out_h[off] = hh;
        out_c[off] = cc;
        if (out_h2) out_h2[off] = hh;
        if (Anext) Anext[off] = rtf(hh);
    }
}

extern "C" void kernel_launch(void* const* d_in, const int* in_sizes, int n_in,
                              void* d_out, int out_size)
{
    (void)in_sizes; (void)n_in; (void)out_size;
    const float* packed_x = (const float*)d_in[0];
    const float* W1   = (const float*)d_in[2];
    const float* bih1 = (const float*)d_in[4];
    const float* bhh1 = (const float*)d_in[5];
    const float* W2   = (const float*)d_in[6];
    const float* bih2 = (const float*)d_in[8];
    const float* bhh2 = (const float*)d_in[9];
    const float* W3   = (const float*)d_in[10];
    const float* bih3 = (const float*)d_in[12];
    const float* bhh3 = (const float*)d_in[13];
    const float* W4   = (const float*)d_in[14];
    const float* bih4 = (const float*)d_in[16];
    const float* bhh4 = (const float*)d_in[17];

    float* out = (float*)d_out;
    const size_t NH = (size_t)NTOK * HID;
    float* o_dup = out;
    float* h1 = out + 1 * NH; float* c1 = out + 2 * NH;
    float* h2 = out + 3 * NH; float* c2 = out + 4 * NH;
    float* h3 = out + 5 * NH; float* c3 = out + 6 * NH;
    float* h4 = out + 7 * NH; float* c4 = out + 8 * NH;

    cudaFuncSetAttribute(lstm_cell_gemm,
                         cudaFuncAttributeMaxDynamicSharedMemorySize, SMEM_BYTES);

    k_build_idx<<<T_STEPS, 128>>>();
    dim3 gw(768, 4);
    k_round_w<<<gw, 256>>>(W1, W2, W3, W4);
    k_gather<<<NPAD, 128>>>(packed_x);

    dim3 grid(HID / BJ, NPAD / BM);   // (16, 256)
    lstm_cell_gemm<<<grid, NTHREADS, SMEM_BYTES>>>(0, bih1, bhh1, h1, c1, nullptr);
    lstm_cell_gemm<<<grid, NTHREADS, SMEM_BYTES>>>(1, bih2, bhh2, h2, c2, nullptr);
    lstm_cell_gemm<<<grid, NTHREADS, SMEM_BYTES>>>(2, bih3, bhh3, h3, c3, nullptr);
    lstm_cell_gemm<<<grid, NTHREADS, SMEM_BYTES>>>(3, bih4, bhh4, h4, c4, o_dup);
}

// round 4
// speedup vs baseline: 1.3280x; 1.0576x over previous
#include <cuda_runtime.h>
#include <math.h>
#include <stdint.h>

#define T_STEPS 512
#define NTOK    32643
#define NPAD    32768
#define HID     512
#define BM 128
#define BJ 32
#define BN 96          // 3 gate strips (i, f-skipped, g, o) of BJ columns each
#define BK 32
#define LDSM 36        // BK + 4 pad; 144B row pitch, 16B aligned, conflict-free ldmatrix
#define NTHREADS 256
#define KTILES (HID / BK)          // 16
#define A_WORDS (BM * LDSM)        // 4608
#define B_WORDS (BN * LDSM)        // 3456
#define SMEM_WORDS (2 * A_WORDS + 2 * B_WORDS)  // 16128 words = 63 KB
#define SMEM_BYTES (SMEM_WORDS * 4)

// ---- persistent scratch ----
__device__ int   g_idx[NTOK];
__device__ float g_A0[(size_t)NPAD * HID];   // ping: tf32-rounded activations
__device__ float g_A1[(size_t)NPAD * HID];   // pong
__device__ float g_W[(size_t)4 * 1536 * HID]; // tf32-rounded W rows (i,g,o) per layer

__device__ __forceinline__ int bsz(int i) {
    int v = (128 * (T_STEPS - i)) >> 9;
    return v < 1 ? 1 : v;
}

__global__ void k_build_idx() {
    __shared__ int off;
    int t = blockIdx.x;
    if (threadIdx.x == 0) {
        int s = 0;
        for (int i = 0; i < t; i++) s += bsz(i);
        off = s;
    }
    __syncthreads();
    int b = bsz(t);
    if ((int)threadIdx.x < b) g_idx[off + threadIdx.x] = t * b + (int)threadIdx.x;
}

__device__ __forceinline__ float rtf(float x) {
    unsigned u;
    asm("cvt.rna.tf32.f32 %0, %1;" : "=r"(u) : "f"(x));
    return __uint_as_float(u);
}

__global__ void k_gather(const float* __restrict__ x) {
    int row = blockIdx.x;
    float4* dst = (float4*)(g_A0 + (size_t)row * HID);
    if (row < NTOK) {
        const float4* src = (const float4*)(x + (size_t)g_idx[row] * HID);
        for (int i = threadIdx.x; i < HID / 4; i += blockDim.x) {
            float4 v = src[i];
            v.x = rtf(v.x); v.y = rtf(v.y); v.z = rtf(v.z); v.w = rtf(v.w);
            dst[i] = v;
        }
    } else {
        for (int i = threadIdx.x; i < HID / 4; i += blockDim.x)
            dst[i] = make_float4(0.f, 0.f, 0.f, 0.f);
    }
}

__global__ void k_round_w(const float* __restrict__ W1, const float* __restrict__ W2,
                          const float* __restrict__ W3, const float* __restrict__ W4) {
    int l = blockIdx.y;
    const float* W = (l == 0) ? W1 : (l == 1) ? W2 : (l == 2) ? W3 : W4;
    int t = blockIdx.x * blockDim.x + threadIdx.x;
    int n = t >> 7;                        // 0..1535
    int col = (t & 127) * 4;
    int srow = n + (n >= 512 ? 512 : 0);   // skip f-gate rows
    float4 v = *(const float4*)(W + (size_t)srow * HID + col);
    v.x = rtf(v.x); v.y = rtf(v.y); v.z = rtf(v.z); v.w = rtf(v.w);
    *(float4*)(g_W + ((size_t)l * 1536 + n) * HID + col) = v;
}

__device__ __forceinline__ void cpa16(unsigned d, const void* s) {
    asm volatile("cp.async.cg.shared.global [%0], [%1], 16;\n" :: "r"(d), "l"(s));
}

__device__ __forceinline__ void ldsm4(uint32_t* r, uint32_t addr) {
    asm volatile("ldmatrix.sync.aligned.m8n8.x4.shared.b16 {%0,%1,%2,%3}, [%4];"
                 : "=r"(r[0]), "=r"(r[1]), "=r"(r[2]), "=r"(r[3]) : "r"(addr));
}

__device__ __forceinline__ void mma8(float* d, const uint32_t* a, const uint32_t* b) {
    asm volatile(
        "mma.sync.aligned.m16n8k8.row.col.f32.tf32.tf32.f32 "
        "{%0,%1,%2,%3}, {%4,%5,%6,%7}, {%8,%9}, {%0,%1,%2,%3};\n"
        : "+f"(d[0]), "+f"(d[1]), "+f"(d[2]), "+f"(d[3])
        : "r"(a[0]), "r"(a[1]), "r"(a[2]), "r"(a[3]), "r"(b[0]), "r"(b[1]));
}

__global__ __launch_bounds__(NTHREADS, 2)
void lstm_cell_gemm(int layer,
                    const float* __restrict__ bih, const float* __restrict__ bhh,
                    float* __restrict__ out_h, float* __restrict__ out_c,
                    float* __restrict__ out_h2)
{
    const float* A     = (layer & 1) ? g_A1 : g_A0;
    float*       Anext = (layer == 3) ? nullptr : ((layer & 1) ? g_A0 : g_A1);
    const float* Wl    = g_W + (size_t)layer * 1536 * HID;

    extern __shared__ __align__(16) float sm[];
    const int bj = blockIdx.x, bm = blockIdx.y;
    const int m0 = bm * BM, j0 = bj * BJ;
    const int tid = threadIdx.x, lane = tid & 31, wid = tid >> 5;
    const int wm = (wid >> 1) * 32;       // 4 warps along m (32 rows each)
    const int wn = (wid & 1) * 48;        // 2 warps along n (48 cols each)

    // ldmatrix per-thread row/col-offset mapping (quad layout, see theory)
    const int tq = lane >> 3, tr = lane & 7;
    const int rowA  = wm + (tq & 1) * 8 + tr;   // + mi*16
    const int koffA = (tq >> 1) * 4;
    const int rowB  = wn + (tq >> 1) * 8 + tr;  // + bi*16
    const int koffB = (tq & 1) * 4;

    // cp.async chunk mapping (16B per thread per chunk)
    const float* asrc[4]; unsigned adst[4];
#pragma unroll
    for (int i = 0; i < 4; i++) {
        int cid = tid + i * NTHREADS;          // 0..1023
        int m = cid >> 3, kc = (cid & 7) * 4;
        asrc[i] = A + (size_t)(m0 + m) * HID + kc;
        adst[i] = (unsigned)(m * LDSM + kc);
    }
    const float* bsrc[3]; unsigned bdst[3];
#pragma unroll
    for (int i = 0; i < 3; i++) {
        int cid = tid + i * NTHREADS;          // 0..767
        int n = cid >> 3, kc = (cid & 7) * 4;
        int wr = (n >> 5) * 512 + j0 + (n & 31);  // strip*512 + j0 + u in g_W layer
        bsrc[i] = Wl + (size_t)wr * HID + kc;
        bdst[i] = (unsigned)(2 * A_WORDS + n * LDSM + kc);
    }
    const unsigned smbase = (unsigned)__cvta_generic_to_shared(sm);

    auto issue = [&](int kt) {
        int s = kt & 1;
        unsigned ab = smbase + (unsigned)(s * A_WORDS) * 4u;
        unsigned bb = smbase + (unsigned)(s * B_WORDS) * 4u;
        const int ko = kt * BK;
#pragma unroll
        for (int i = 0; i < 4; i++) cpa16(ab + adst[i] * 4u, asrc[i] + ko);
#pragma unroll
        for (int i = 0; i < 3; i++) cpa16(bb + bdst[i] * 4u, bsrc[i] + ko);
        asm volatile("cp.async.commit_group;\n");
    };

    float acc[2][6][4];
#pragma unroll
    for (int mi = 0; mi < 2; mi++)
#pragma unroll
        for (int ni = 0; ni < 6; ni++)
#pragma unroll
            for (int q = 0; q < 4; q++) acc[mi][ni][q] = 0.f;

    issue(0);

#pragma unroll 1
    for (int kt = 0; kt < KTILES; kt++) {
        asm volatile("cp.async.wait_group 0;\n");
        __syncthreads();
        if (kt + 1 < KTILES) issue(kt + 1);

        const unsigned abase = smbase + (unsigned)((kt & 1) * A_WORDS) * 4u;
        const unsigned bbase = smbase + (unsigned)(2 * A_WORDS + (kt & 1) * B_WORDS) * 4u;
#pragma unroll
        for (int ks = 0; ks < BK / 8; ks++) {
            const int kb = ks * 8;
            uint32_t af[2][4], bq[3][4];
#pragma unroll
            for (int mi = 0; mi < 2; mi++)
                ldsm4(af[mi], abase + (unsigned)(((rowA + mi * 16) * LDSM) + kb + koffA) * 4u);
#pragma unroll
            for (int bi = 0; bi < 3; bi++)
                ldsm4(bq[bi], bbase + (unsigned)(((rowB + bi * 16) * LDSM) + kb + koffB) * 4u);
#pragma unroll
            for (int mi = 0; mi < 2; mi++)
#pragma unroll
                for (int ni = 0; ni < 6; ni++)
                    mma8(acc[mi][ni], af[mi], &bq[ni >> 1][(ni & 1) * 2]);
        }
    }
    __syncthreads();   // all compute done before smem reuse

    // ---- epilogue: stage gates (i,g,o strips) in smem, then fused pointwise ----
    float* Gs = sm;    // [BM][98] = 12544 words <= 16128
    const int r = lane >> 2, c = lane & 3;
#pragma unroll
    for (int mi = 0; mi < 2; mi++) {
#pragma unroll
        for (int ni = 0; ni < 6; ni++) {
            int row = wm + mi * 16 + r;
            int col = wn + ni * 8 + 2 * c;
            *(float2*)&Gs[row * 98 + col]       = make_float2(acc[mi][ni][0], acc[mi][ni][1]);
            *(float2*)&Gs[(row + 8) * 98 + col] = make_float2(acc[mi][ni][2], acc[mi][ni][3]);
        }
    }
    __syncthreads();

    for (int e = tid; e < BM * BJ; e += NTHREADS) {
        int m = e >> 5, j = e & 31;
        int gm = m0 + m;
        if (gm >= NTOK) continue;
        int jg = j0 + j;
        float iv = Gs[m * 98 + j]      + bih[jg]        + bhh[jg];
        float gv = Gs[m * 98 + 32 + j] + bih[1024 + jg] + bhh[1024 + jg];
        float ov = Gs[m * 98 + 64 + j] + bih[1536 + jg] + bhh[1536 + jg];
        float cc = (1.f / (1.f + __expf(-iv))) * tanhf(gv);
        float hh = (1.f / (1.f + __expf(-ov))) * tanhf(cc);
        size_t off = (size_t)gm * HID + jg;
        out_h[off] = hh;
        out_c[off] = cc;
        if (out_h2) out_h2[off] = hh;
        if (Anext) Anext[off] = rtf(hh);
    }
}

extern "C" void kernel_launch(void* const* d_in, const int* in_sizes, int n_in,
                              void* d_out, int out_size)
{
    (void)in_sizes; (void)n_in; (void)out_size;
    const float* packed_x = (const float*)d_in[0];
    const float* W1   = (const float*)d_in[2];
    const float* bih1 = (const float*)d_in[4];
    const float* bhh1 = (const float*)d_in[5];
    const float* W2   = (const float*)d_in[6];
    const float* bih2 = (const float*)d_in[8];
    const float* bhh2 = (const float*)d_in[9];
    const float* W3   = (const float*)d_in[10];
    const float* bih3 = (const float*)d_in[12];
    const float* bhh3 = (const float*)d_in[13];
    const float* W4   = (const float*)d_in[14];
    const float* bih4 = (const float*)d_in[16];
    const float* bhh4 = (const float*)d_in[17];

    float* out = (float*)d_out;
    const size_t NH = (size_t)NTOK * HID;
    float* o_dup = out;
    float* h1 = out + 1 * NH; float* c1 = out + 2 * NH;
    float* h2 = out + 3 * NH; float* c2 = out + 4 * NH;
    float* h3 = out + 5 * NH; float* c3 = out + 6 * NH;
    float* h4 = out + 7 * NH; float* c4 = out + 8 * NH;

    cudaFuncSetAttribute(lstm_cell_gemm,
                         cudaFuncAttributeMaxDynamicSharedMemorySize, SMEM_BYTES);

    k_build_idx<<<T_STEPS, 128>>>();
    dim3 gw(768, 4);
    k_round_w<<<gw, 256>>>(W1, W2, W3, W4);
    k_gather<<<NPAD, 128>>>(packed_x);

    dim3 grid(HID / BJ, NPAD / BM);   // (16, 256)
    lstm_cell_gemm<<<grid, NTHREADS, SMEM_BYTES>>>(0, bih1, bhh1, h1, c1, nullptr);
    lstm_cell_gemm<<<grid, NTHREADS, SMEM_BYTES>>>(1, bih2, bhh2, h2, c2, nullptr);
    lstm_cell_gemm<<<grid, NTHREADS, SMEM_BYTES>>>(2, bih3, bhh3, h3, c3, nullptr);
    lstm_cell_gemm<<<grid, NTHREADS, SMEM_BYTES>>>(3, bih4, bhh4, h4, c4, o_dup);
}